// round 5
// baseline (speedup 1.0000x reference)
#include <cuda_runtime.h>
#include <math.h>

#define NN   6000
#define EE   192000
#define DIN  512
#define HH   128
#define NPB  8           // nodes per block in p-kernel
#define EOSF 1e-10f
#define CHUNK 65536ull   // TMA bulk-store chunk (bytes), fits SMEM

// Scratch (__device__ globals allowed; heap allocs are not).
__device__ int   g_win[(size_t)NN * NN];   // winner edge-index+1 per cell (only edge cells touched)
__device__ float g_p[NN];
__device__ float g_dlp[NN];
__device__ float g_dhp[NN];
__device__ float g_ilp[NN];
__device__ float g_ihp[NN];

// Zero fill via TMA bulk stores: full-line async-proxy writes, no read-allocate.
__global__ void __launch_bounds__(128) k_fill_tma(char* __restrict__ dst,
                                                  unsigned long long nbytes) {
    __shared__ __align__(128) char buf[CHUNK];
    float4* b4 = (float4*)buf;
    const float4 z = make_float4(0.f, 0.f, 0.f, 0.f);
    for (unsigned i = threadIdx.x; i < CHUNK / 16; i += 128) b4[i] = z;
    // Make generic-proxy smem writes visible to the async proxy.
    asm volatile("fence.proxy.async.shared::cta;" ::: "memory");
    __syncthreads();

    if (threadIdx.x == 0) {
        unsigned smem_addr;
        asm("{ .reg .u64 t; cvta.to.shared.u64 t, %1; cvt.u32.u64 %0, t; }"
            : "=r"(smem_addr) : "l"(buf));
        unsigned long long stride = (unsigned long long)gridDim.x * CHUNK;
        for (unsigned long long off = (unsigned long long)blockIdx.x * CHUNK;
             off < nbytes; off += stride) {
            unsigned sz = (unsigned)((nbytes - off < CHUNK) ? (nbytes - off) : CHUNK);
            asm volatile("cp.async.bulk.global.shared::cta.bulk_group [%0], [%1], %2;"
                         :: "l"(dst + off), "r"(smem_addr), "r"(sz) : "memory");
            asm volatile("cp.async.bulk.commit_group;" ::: "memory");
            asm volatile("cp.async.bulk.wait_group 8;" ::: "memory");  // cap in-flight
        }
        asm volatile("cp.async.bulk.wait_group 0;" ::: "memory");
    }
}

// Clear winner at all edge cells; init degrees to 1.0 (the +eye term in row sums).
__global__ void k_clear(const int* __restrict__ edges) {
    int t = blockIdx.x * blockDim.x + threadIdx.x;
    if (t < EE) {
        int u = edges[t], v = edges[EE + t];
        g_win[u * NN + v] = 0;
    }
    if (t < NN) { g_dlp[t] = 1.0f; g_dhp[t] = 1.0f; }
}

// Last-edge-wins dedup: winner = max edge index + 1.
__global__ void k_max(const int* __restrict__ edges) {
    int e = blockIdx.x * blockDim.x + threadIdx.x;
    if (e >= EE) return;
    int u = edges[e], v = edges[EE + e];
    atomicMax(&g_win[u * NN + v], e + 1);
}

// p[n] = sum_h relu(feat[n]·w_emb[:,h] + b_emb[h]) * (w_mlp[h] + w_mlp[H+h])
__global__ void __launch_bounds__(HH) k_p(const float* __restrict__ feat,
                                          const float* __restrict__ wemb,
                                          const float* __restrict__ bemb,
                                          const float* __restrict__ wmlp) {
    __shared__ float sf[NPB][DIN];
    int h  = threadIdx.x;
    int n0 = blockIdx.x * NPB;

    const float4* f4 = (const float4*)(feat + (size_t)n0 * DIN);
    float4* s4 = (float4*)&sf[0][0];
    const int total4 = NPB * DIN / 4;
    for (int i = h; i < total4; i += HH) s4[i] = f4[i];
    __syncthreads();

    float acc[NPB];
#pragma unroll
    for (int j = 0; j < NPB; j++) acc[j] = 0.0f;

    for (int d = 0; d < DIN; d += 4) {
        float w0 = wemb[(d + 0) * HH + h];
        float w1 = wemb[(d + 1) * HH + h];
        float w2 = wemb[(d + 2) * HH + h];
        float w3 = wemb[(d + 3) * HH + h];
#pragma unroll
        for (int j = 0; j < NPB; j++) {
            float4 f = *(const float4*)&sf[j][d];
            acc[j] = fmaf(f.x, w0, acc[j]);
            acc[j] = fmaf(f.y, w1, acc[j]);
            acc[j] = fmaf(f.z, w2, acc[j]);
            acc[j] = fmaf(f.w, w3, acc[j]);
        }
    }

    float b  = bemb[h];
    float ws = wmlp[h] + wmlp[HH + h];
    __shared__ float red[4][NPB];
#pragma unroll
    for (int j = 0; j < NPB; j++) {
        float v = acc[j] + b;
        v = (v > 0.0f) ? v * ws : 0.0f;
#pragma unroll
        for (int off = 16; off; off >>= 1) v += __shfl_down_sync(0xffffffffu, v, off);
        if ((h & 31) == 0) red[h >> 5][j] = v;
    }
    __syncthreads();
    if (h < NPB)
        g_p[n0 + h] = red[0][h] + red[1][h] + red[2][h] + red[3][h];
}

// Per-edge gating weights + winner-only degree accumulation (row sums).
__global__ void k_edge(const int* __restrict__ edges, const float* __restrict__ gn,
                       const float* __restrict__ bmlp,
                       float* __restrict__ wlp_out, float* __restrict__ whp_out) {
    int e = blockIdx.x * blockDim.x + threadIdx.x;
    if (e >= EE) return;
    int u = edges[e], v = edges[EE + e];
    float raw = 0.5f * (g_p[u] + g_p[v]) + bmlp[0];
    float x   = gn[e] + raw;               // TEMP = 1
    float wlp = 1.0f / (1.0f + expf(-x));
    wlp_out[e] = wlp;
    whp_out[e] = 1.0f - wlp;
    if (g_win[u * NN + v] == e + 1) {       // deduped adjacency contribution
        atomicAdd(&g_dlp[u], wlp);
        atomicAdd(&g_dhp[u], 1.0f - wlp);
    }
}

__global__ void k_inv() {
    int i = blockIdx.x * blockDim.x + threadIdx.x;
    if (i >= NN) return;
    g_ilp[i] = 1.0f / (sqrtf(g_dlp[i]) + EOSF);
    g_ihp[i] = 1.0f / (sqrtf(g_dhp[i]) + EOSF);
}

// Unnorm/mask scatter: duplicates write the same value.
__global__ void k_fin_unnorm(const int* __restrict__ edges, float* __restrict__ unnorm) {
    int t = blockIdx.x * blockDim.x + threadIdx.x;
    if (t >= EE) return;
    int u = edges[t], v = edges[EE + t];
    __stcs(&unnorm[(size_t)u * NN + v], 1.0f);
}

// Adjacency scatter + diagonal. Pure stores, no RMW (self-edge case closed-form).
__global__ void k_fin_adj(const int* __restrict__ edges, const float* __restrict__ wlp_out,
                          float* __restrict__ adj_lp, float* __restrict__ adj_hp) {
    int t = blockIdx.x * blockDim.x + threadIdx.x;
    if (t < EE) {
        int u = edges[t], v = edges[EE + t];
        size_t cell = (size_t)u * NN + v;
        if (g_win[cell] == t + 1) {
            float wlp = wlp_out[t];
            float il = g_ilp[u] * g_ilp[v];
            float ih = g_ihp[u] * g_ihp[v];
            if (u == v) {
                __stcs(&adj_lp[cell], (1.0f + wlp) * il);          // eye + self-edge, normalized
                __stcs(&adj_hp[cell], 1.0f - (2.0f - wlp) * ih);   // 1 - (whp + 1)*ih
            } else {
                __stcs(&adj_lp[cell], wlp * il);
                __stcs(&adj_hp[cell], -(1.0f - wlp) * ih);
            }
        }
    } else if (t < EE + NN) {
        int i = t - EE;
        size_t cell = (size_t)i * NN + i;
        if (g_win[cell] == 0) {              // no self-edge at (i,i)
            float il = g_ilp[i];
            __stcs(&adj_lp[cell], il * il);
            __stcs(&adj_hp[cell], 1.0f);
        }
    }
}

extern "C" void kernel_launch(void* const* d_in, const int* in_sizes, int n_in,
                              void* d_out, int out_size) {
    const float* feat  = (const float*)d_in[0];
    const int*   edges = (const int*)  d_in[1];
    const float* wemb  = (const float*)d_in[2];
    const float* bemb  = (const float*)d_in[3];
    const float* wmlp  = (const float*)d_in[4];
    const float* bmlp  = (const float*)d_in[5];
    const float* gn    = (const float*)d_in[6];

    float* out     = (float*)d_out;
    float* adj_lp  = out;
    float* adj_hp  = out + (size_t)NN * NN;
    float* wlp     = out + 2ull * NN * NN;
    float* whp     = wlp + EE;
    float* unnorm  = whp + EE;

    static cudaStream_t s_fill = nullptr, s_fill2 = nullptr, s_p = nullptr;
    static cudaEvent_t ev_fork = nullptr, ev_fu = nullptr, ev_fa = nullptr,
                       ev_p = nullptr, ev_un = nullptr;
    if (!s_fill) {
        cudaStreamCreateWithFlags(&s_fill,  cudaStreamNonBlocking);
        cudaStreamCreateWithFlags(&s_fill2, cudaStreamNonBlocking);
        cudaStreamCreateWithFlags(&s_p,     cudaStreamNonBlocking);
        cudaEventCreateWithFlags(&ev_fork, cudaEventDisableTiming);
        cudaEventCreateWithFlags(&ev_fu,   cudaEventDisableTiming);
        cudaEventCreateWithFlags(&ev_fa,   cudaEventDisableTiming);
        cudaEventCreateWithFlags(&ev_p,    cudaEventDisableTiming);
        cudaEventCreateWithFlags(&ev_un,   cudaEventDisableTiming);
    }

    const int TB = 256;

    // Fork.
    cudaEventRecord(ev_fork, 0);
    cudaStreamWaitEvent(s_fill,  ev_fork, 0);
    cudaStreamWaitEvent(s_fill2, ev_fork, 0);
    cudaStreamWaitEvent(s_p,     ev_fork, 0);

    // TMA bulk-store zero fills: adj (288 MB) and unnorm (144 MB) concurrently.
    k_fill_tma<<<148, 128, 0, s_fill>>>((char*)adj_lp, 2ull * NN * NN * sizeof(float));
    cudaEventRecord(ev_fa, s_fill);
    k_fill_tma<<<74, 128, 0, s_fill2>>>((char*)unnorm, (size_t)NN * NN * sizeof(float));
    cudaEventRecord(ev_fu, s_fill2);

    // Side stream: node scalar projection, then unnorm scatter once its fill lands.
    k_p<<<NN / NPB, HH, 0, s_p>>>(feat, wemb, bemb, wmlp);
    cudaEventRecord(ev_p, s_p);
    cudaStreamWaitEvent(s_p, ev_fu, 0);
    k_fin_unnorm<<<(EE + TB - 1) / TB, TB, 0, s_p>>>(edges, unnorm);
    cudaEventRecord(ev_un, s_p);

    // Main chain: winner bookkeeping, gating, norms (all overlap the fills).
    k_clear<<<(EE + TB - 1) / TB, TB>>>(edges);
    k_max  <<<(EE + TB - 1) / TB, TB>>>(edges);
    cudaStreamWaitEvent(0, ev_p, 0);
    k_edge<<<(EE + TB - 1) / TB, TB>>>(edges, gn, bmlp, wlp, whp);
    k_inv <<<(NN + TB - 1) / TB, TB>>>();

    // Join adj fill, then the adjacency scatter tail.
    cudaStreamWaitEvent(0, ev_fa, 0);
    k_fin_adj<<<(EE + NN + TB - 1) / TB, TB>>>(edges, wlp, adj_lp, adj_hp);

    // Join the unnorm branch so the graph has a single terminal.
    cudaStreamWaitEvent(0, ev_un, 0);
}

// round 6
// speedup vs baseline: 1.0528x; 1.0528x over previous
#include <cuda_runtime.h>
#include <math.h>

#define NN   6000
#define EE   192000
#define DIN  512
#define HH   128
#define NPB  8           // nodes per block in p-kernel
#define EOSF 1e-10f

// Scratch (__device__ globals allowed; heap allocs are not).
__device__ int   g_win[(size_t)NN * NN];   // winner edge-index+1 per cell (only edge cells touched)
__device__ float g_p[NN];
__device__ float g_dlp[NN];
__device__ float g_dhp[NN];
__device__ float g_ilp[NN];
__device__ float g_ihp[NN];

// Zero fill with write-through stores: bypass L2 store-miss allocation
// (the suspected source of the 2x DRAM traffic on every other store path).
__global__ void __launch_bounds__(512) k_fill(float4* __restrict__ dst, size_t n4) {
    size_t i = (size_t)blockIdx.x * blockDim.x + threadIdx.x;
    size_t stride = (size_t)gridDim.x * blockDim.x;
    const float4 z = make_float4(0.f, 0.f, 0.f, 0.f);
    for (; i < n4; i += stride) __stwt(dst + i, z);
}

// Clear winner at all edge cells; init degrees to 1.0 (the +eye term in row sums).
__global__ void k_clear(const int* __restrict__ edges) {
    int t = blockIdx.x * blockDim.x + threadIdx.x;
    if (t < EE) {
        int u = edges[t], v = edges[EE + t];
        g_win[u * NN + v] = 0;
    }
    if (t < NN) { g_dlp[t] = 1.0f; g_dhp[t] = 1.0f; }
}

// Last-edge-wins dedup: winner = max edge index + 1.
__global__ void k_max(const int* __restrict__ edges) {
    int e = blockIdx.x * blockDim.x + threadIdx.x;
    if (e >= EE) return;
    int u = edges[e], v = edges[EE + e];
    atomicMax(&g_win[u * NN + v], e + 1);
}

// p[n] = sum_h relu(feat[n]·w_emb[:,h] + b_emb[h]) * (w_mlp[h] + w_mlp[H+h])
__global__ void __launch_bounds__(HH) k_p(const float* __restrict__ feat,
                                          const float* __restrict__ wemb,
                                          const float* __restrict__ bemb,
                                          const float* __restrict__ wmlp) {
    __shared__ float sf[NPB][DIN];
    int h  = threadIdx.x;
    int n0 = blockIdx.x * NPB;

    const float4* f4 = (const float4*)(feat + (size_t)n0 * DIN);
    float4* s4 = (float4*)&sf[0][0];
    const int total4 = NPB * DIN / 4;
    for (int i = h; i < total4; i += HH) s4[i] = f4[i];
    __syncthreads();

    float acc[NPB];
#pragma unroll
    for (int j = 0; j < NPB; j++) acc[j] = 0.0f;

    for (int d = 0; d < DIN; d += 4) {
        float w0 = wemb[(d + 0) * HH + h];
        float w1 = wemb[(d + 1) * HH + h];
        float w2 = wemb[(d + 2) * HH + h];
        float w3 = wemb[(d + 3) * HH + h];
#pragma unroll
        for (int j = 0; j < NPB; j++) {
            float4 f = *(const float4*)&sf[j][d];
            acc[j] = fmaf(f.x, w0, acc[j]);
            acc[j] = fmaf(f.y, w1, acc[j]);
            acc[j] = fmaf(f.z, w2, acc[j]);
            acc[j] = fmaf(f.w, w3, acc[j]);
        }
    }

    float b  = bemb[h];
    float ws = wmlp[h] + wmlp[HH + h];
    __shared__ float red[4][NPB];
#pragma unroll
    for (int j = 0; j < NPB; j++) {
        float v = acc[j] + b;
        v = (v > 0.0f) ? v * ws : 0.0f;
#pragma unroll
        for (int off = 16; off; off >>= 1) v += __shfl_down_sync(0xffffffffu, v, off);
        if ((h & 31) == 0) red[h >> 5][j] = v;
    }
    __syncthreads();
    if (h < NPB)
        g_p[n0 + h] = red[0][h] + red[1][h] + red[2][h] + red[3][h];
}

// Per-edge gating weights + winner-only degree accumulation (row sums).
__global__ void k_edge(const int* __restrict__ edges, const float* __restrict__ gn,
                       const float* __restrict__ bmlp,
                       float* __restrict__ wlp_out, float* __restrict__ whp_out) {
    int e = blockIdx.x * blockDim.x + threadIdx.x;
    if (e >= EE) return;
    int u = edges[e], v = edges[EE + e];
    float raw = 0.5f * (g_p[u] + g_p[v]) + bmlp[0];
    float x   = gn[e] + raw;               // TEMP = 1
    float wlp = 1.0f / (1.0f + expf(-x));
    wlp_out[e] = wlp;
    whp_out[e] = 1.0f - wlp;
    if (g_win[u * NN + v] == e + 1) {       // deduped adjacency contribution
        atomicAdd(&g_dlp[u], wlp);
        atomicAdd(&g_dhp[u], 1.0f - wlp);
    }
}

__global__ void k_inv() {
    int i = blockIdx.x * blockDim.x + threadIdx.x;
    if (i >= NN) return;
    g_ilp[i] = 1.0f / (sqrtf(g_dlp[i]) + EOSF);
    g_ihp[i] = 1.0f / (sqrtf(g_dhp[i]) + EOSF);
}

// Unnorm/mask scatter: duplicates write the same value.
__global__ void k_fin_unnorm(const int* __restrict__ edges, float* __restrict__ unnorm) {
    int t = blockIdx.x * blockDim.x + threadIdx.x;
    if (t >= EE) return;
    int u = edges[t], v = edges[EE + t];
    __stcs(&unnorm[(size_t)u * NN + v], 1.0f);
}

// Adjacency scatter + diagonal. Pure stores, no RMW (self-edge case closed-form).
__global__ void k_fin_adj(const int* __restrict__ edges, const float* __restrict__ wlp_out,
                          float* __restrict__ adj_lp, float* __restrict__ adj_hp) {
    int t = blockIdx.x * blockDim.x + threadIdx.x;
    if (t < EE) {
        int u = edges[t], v = edges[EE + t];
        size_t cell = (size_t)u * NN + v;
        if (g_win[cell] == t + 1) {
            float wlp = wlp_out[t];
            float il = g_ilp[u] * g_ilp[v];
            float ih = g_ihp[u] * g_ihp[v];
            if (u == v) {
                __stcs(&adj_lp[cell], (1.0f + wlp) * il);          // eye + self-edge, normalized
                __stcs(&adj_hp[cell], 1.0f - (2.0f - wlp) * ih);   // 1 - (whp + 1)*ih
            } else {
                __stcs(&adj_lp[cell], wlp * il);
                __stcs(&adj_hp[cell], -(1.0f - wlp) * ih);
            }
        }
    } else if (t < EE + NN) {
        int i = t - EE;
        size_t cell = (size_t)i * NN + i;
        if (g_win[cell] == 0) {              // no self-edge at (i,i)
            float il = g_ilp[i];
            __stcs(&adj_lp[cell], il * il);
            __stcs(&adj_hp[cell], 1.0f);
        }
    }
}

extern "C" void kernel_launch(void* const* d_in, const int* in_sizes, int n_in,
                              void* d_out, int out_size) {
    const float* feat  = (const float*)d_in[0];
    const int*   edges = (const int*)  d_in[1];
    const float* wemb  = (const float*)d_in[2];
    const float* bemb  = (const float*)d_in[3];
    const float* wmlp  = (const float*)d_in[4];
    const float* bmlp  = (const float*)d_in[5];
    const float* gn    = (const float*)d_in[6];

    float* out     = (float*)d_out;
    float* adj_lp  = out;
    float* adj_hp  = out + (size_t)NN * NN;
    float* wlp     = out + 2ull * NN * NN;
    float* whp     = wlp + EE;
    float* unnorm  = whp + EE;

    static cudaStream_t s_fill = nullptr, s_p = nullptr;
    static cudaEvent_t ev_fork = nullptr, ev_fu = nullptr, ev_fa = nullptr,
                       ev_p = nullptr, ev_un = nullptr;
    if (!s_fill) {
        cudaStreamCreateWithFlags(&s_fill, cudaStreamNonBlocking);
        cudaStreamCreateWithFlags(&s_p,    cudaStreamNonBlocking);
        cudaEventCreateWithFlags(&ev_fork, cudaEventDisableTiming);
        cudaEventCreateWithFlags(&ev_fu,   cudaEventDisableTiming);
        cudaEventCreateWithFlags(&ev_fa,   cudaEventDisableTiming);
        cudaEventCreateWithFlags(&ev_p,    cudaEventDisableTiming);
        cudaEventCreateWithFlags(&ev_un,   cudaEventDisableTiming);
    }

    const int TB = 256;

    // Fork.
    cudaEventRecord(ev_fork, 0);
    cudaStreamWaitEvent(s_fill, ev_fork, 0);
    cudaStreamWaitEvent(s_p,    ev_fork, 0);

    // Side stream 1: write-through zero fills. Unnorm first (its scatter has no
    // other dependencies), then the two adjacency matrices (contiguous).
    k_fill<<<148 * 8,  512, 0, s_fill>>>((float4*)unnorm, ((size_t)NN * NN) / 4);
    cudaEventRecord(ev_fu, s_fill);
    k_fill<<<148 * 16, 512, 0, s_fill>>>((float4*)adj_lp, (2ull * NN * NN) / 4);
    cudaEventRecord(ev_fa, s_fill);

    // Side stream 2: node scalar projection, then unnorm scatter once its fill lands.
    k_p<<<NN / NPB, HH, 0, s_p>>>(feat, wemb, bemb, wmlp);
    cudaEventRecord(ev_p, s_p);
    cudaStreamWaitEvent(s_p, ev_fu, 0);
    k_fin_unnorm<<<(EE + TB - 1) / TB, TB, 0, s_p>>>(edges, unnorm);
    cudaEventRecord(ev_un, s_p);

    // Main chain: winner bookkeeping, gating, norms (all overlap the fills).
    k_clear<<<(EE + TB - 1) / TB, TB>>>(edges);
    k_max  <<<(EE + TB - 1) / TB, TB>>>(edges);
    cudaStreamWaitEvent(0, ev_p, 0);
    k_edge<<<(EE + TB - 1) / TB, TB>>>(edges, gn, bmlp, wlp, whp);
    k_inv <<<(NN + TB - 1) / TB, TB>>>();

    // Join adj fill, then the adjacency scatter tail.
    cudaStreamWaitEvent(0, ev_fa, 0);
    k_fin_adj<<<(EE + NN + TB - 1) / TB, TB>>>(edges, wlp, adj_lp, adj_hp);

    // Join the unnorm branch so the graph has a single terminal.
    cudaStreamWaitEvent(0, ev_un, 0);
}